// round 1
// baseline (speedup 1.0000x reference)
#include <cuda_runtime.h>

#define NN 10000
#define TT 2
#define CC 64
#define HH 4
#define CO 64
#define HC 256
#define EE 160000
#define MROWS (TT*NN)

// scratch (static device allocations; no cudaMalloc allowed)
__device__ float g_xl[MROWS * HC];
__device__ float g_xr[MROWS * HC];
__device__ float g_alpha[TT * EE * HH];
__device__ int   g_deg[NN];
__device__ int   g_rowptr[NN + 1];
__device__ int   g_cursor[NN];
__device__ int   g_srcs[EE];

__device__ __forceinline__ void atomicMaxF(float* a, float v) {
    int old = __float_as_int(*a);
    while (__int_as_float(old) < v) {
        int assumed = old;
        old = atomicCAS((int*)a, assumed, __float_as_int(v));
        if (old == assumed) break;
    }
}

__global__ void k_zero() {
    int i = blockIdx.x * blockDim.x + threadIdx.x;
    if (i < NN) g_deg[i] = 0;
}

__global__ void k_hist(const int* __restrict__ ei) {
    int e = blockIdx.x * blockDim.x + threadIdx.x;
    if (e < EE) atomicAdd(&g_deg[ei[EE + e]], 1);
}

__global__ void __launch_bounds__(1024) k_scan() {
    __shared__ int sc[1024];
    int tid = threadIdx.x;
    const int CH = (NN + 1023) / 1024;  // 10
    int base = tid * CH;
    int local = 0;
    for (int j = 0; j < CH; j++) {
        int idx = base + j;
        if (idx < NN) local += g_deg[idx];
    }
    sc[tid] = local;
    __syncthreads();
    for (int off = 1; off < 1024; off <<= 1) {
        int v = (tid >= off) ? sc[tid - off] : 0;
        __syncthreads();
        sc[tid] += v;
        __syncthreads();
    }
    int run = sc[tid] - local;  // exclusive prefix
    for (int j = 0; j < CH; j++) {
        int idx = base + j;
        if (idx < NN) {
            g_rowptr[idx] = run;
            g_cursor[idx] = run;
            run += g_deg[idx];
        }
    }
    if (tid == 1023) g_rowptr[NN] = sc[1023];
}

__global__ void k_scatter(const int* __restrict__ ei) {
    int e = blockIdx.x * blockDim.x + threadIdx.x;
    if (e < EE) {
        int d = ei[EE + e];
        int s = ei[e];
        int pos = atomicAdd(&g_cursor[d], 1);
        g_srcs[pos] = s;
    }
}

// Dual GEMM: x_l = x@W_l + b_l,  x_r = x@W_r + b_r.
// Block = 32 rows x 256 cols, 256 threads.
// Thread: rg = tid>>6 (8 rows each), c4 = tid&63 (4 cols via float4), both mats.
__global__ void __launch_bounds__(256) k_gemm(
    const float* __restrict__ x,
    const float* __restrict__ Wl, const float* __restrict__ bl,
    const float* __restrict__ Wr, const float* __restrict__ br)
{
    __shared__ float xs[32][64];
    int tid = threadIdx.x;
    int row0 = blockIdx.x * 32;
    for (int i = tid; i < 32 * 64; i += 256) {
        xs[i >> 6][i & 63] = x[(row0 + (i >> 6)) * CC + (i & 63)];
    }
    __syncthreads();
    int c4 = tid & 63;
    int rg = tid >> 6;
    float4 accl[8], accr[8];
#pragma unroll
    for (int r = 0; r < 8; r++) {
        accl[r] = make_float4(0.f, 0.f, 0.f, 0.f);
        accr[r] = make_float4(0.f, 0.f, 0.f, 0.f);
    }
    const float4* Wl4 = (const float4*)Wl;
    const float4* Wr4 = (const float4*)Wr;
#pragma unroll 8
    for (int k = 0; k < 64; k++) {
        float4 wl = Wl4[k * 64 + c4];
        float4 wr = Wr4[k * 64 + c4];
#pragma unroll
        for (int r = 0; r < 8; r++) {
            float xv = xs[rg * 8 + r][k];
            accl[r].x = fmaf(xv, wl.x, accl[r].x);
            accl[r].y = fmaf(xv, wl.y, accl[r].y);
            accl[r].z = fmaf(xv, wl.z, accl[r].z);
            accl[r].w = fmaf(xv, wl.w, accl[r].w);
            accr[r].x = fmaf(xv, wr.x, accr[r].x);
            accr[r].y = fmaf(xv, wr.y, accr[r].y);
            accr[r].z = fmaf(xv, wr.z, accr[r].z);
            accr[r].w = fmaf(xv, wr.w, accr[r].w);
        }
    }
    float4 bl4 = ((const float4*)bl)[c4];
    float4 br4 = ((const float4*)br)[c4];
#pragma unroll
    for (int r = 0; r < 8; r++) {
        int row = row0 + rg * 8 + r;
        float4 ol, orr;
        ol.x = accl[r].x + bl4.x; ol.y = accl[r].y + bl4.y;
        ol.z = accl[r].z + bl4.z; ol.w = accl[r].w + bl4.w;
        orr.x = accr[r].x + br4.x; orr.y = accr[r].y + br4.y;
        orr.z = accr[r].z + br4.z; orr.w = accr[r].w + br4.w;
        ((float4*)g_xl)[row * 64 + c4] = ol;
        ((float4*)g_xr)[row * 64 + c4] = orr;
    }
}

// One block per (t, n). 256 threads = 8 warps.
__global__ void __launch_bounds__(256) k_node(
    const float* __restrict__ x,
    const float* __restrict__ att,
    const float* __restrict__ bias,
    const float* __restrict__ Wp, const float* __restrict__ bp,
    const float* __restrict__ gam, const float* __restrict__ bet,
    float* __restrict__ out)
{
    int n = blockIdx.x;
    int t = blockIdx.y;
    int tid = threadIdx.x;
    int lane = tid & 31;
    int wid = tid >> 5;
    int h = tid >> 6;

    __shared__ __align__(16) float xr_s[256];
    __shared__ float hmax[4];
    __shared__ float hsum[4];
    __shared__ float out_s[256];
    __shared__ float pp[4][64];
    __shared__ float red[2][2];

    int rowbase = (t * NN + n) * HC;
    xr_s[tid] = g_xr[rowbase + tid];
    if (tid < 4) { hmax[tid] = -1e30f; hsum[tid] = 0.f; }
    int base = g_rowptr[n];
    int deg = g_rowptr[n + 1] - base;
    int abase = (t * EE + base) * HH;
    __syncthreads();

    // ---- loop1: warp-per-edge alpha computation + warp-local max ----
    {
        float4 xr0 = *(const float4*)&xr_s[lane * 4];
        float4 xr1 = *(const float4*)&xr_s[128 + lane * 4];
        float4 at0 = ((const float4*)att)[lane];
        float4 at1 = ((const float4*)att)[32 + lane];
        float m0 = -1e30f, m1 = -1e30f;
        for (int k = wid; k < deg; k += 8) {
            int s = g_srcs[base + k];
            const float4* xl = (const float4*)&g_xl[(t * NN + s) * HC];
            float4 a0 = xl[lane];
            float4 a1 = xl[32 + lane];
            float v, p0, p1;
            v = a0.x + xr0.x; v = fmaxf(v, 0.2f * v); p0 = v * at0.x;
            v = a0.y + xr0.y; v = fmaxf(v, 0.2f * v); p0 = fmaf(v, at0.y, p0);
            v = a0.z + xr0.z; v = fmaxf(v, 0.2f * v); p0 = fmaf(v, at0.z, p0);
            v = a0.w + xr0.w; v = fmaxf(v, 0.2f * v); p0 = fmaf(v, at0.w, p0);
            v = a1.x + xr1.x; v = fmaxf(v, 0.2f * v); p1 = v * at1.x;
            v = a1.y + xr1.y; v = fmaxf(v, 0.2f * v); p1 = fmaf(v, at1.y, p1);
            v = a1.z + xr1.z; v = fmaxf(v, 0.2f * v); p1 = fmaf(v, at1.z, p1);
            v = a1.w + xr1.w; v = fmaxf(v, 0.2f * v); p1 = fmaf(v, at1.w, p1);
            // reduce within 16-lane halves (h0/h2 on lanes 0-15, h1/h3 on 16-31)
#pragma unroll
            for (int off = 8; off; off >>= 1) {
                p0 += __shfl_xor_sync(0xffffffffu, p0, off);
                p1 += __shfl_xor_sync(0xffffffffu, p1, off);
            }
            m0 = fmaxf(m0, p0);
            m1 = fmaxf(m1, p1);
            if (lane == 0) {
                g_alpha[abase + k * 4 + 0] = p0;
                g_alpha[abase + k * 4 + 2] = p1;
            } else if (lane == 16) {
                g_alpha[abase + k * 4 + 1] = p0;
                g_alpha[abase + k * 4 + 3] = p1;
            }
        }
        if (lane == 0)       { atomicMaxF(&hmax[0], m0); atomicMaxF(&hmax[2], m1); }
        else if (lane == 16) { atomicMaxF(&hmax[1], m0); atomicMaxF(&hmax[3], m1); }
    }
    __syncthreads();

    // ---- loop2: exp + denom; overwrite alpha with exp(alpha - max) ----
    for (int i = tid; i < deg * HH; i += 256) {
        float a = g_alpha[abase + i];
        float e = __expf(a - hmax[i & 3]);
        g_alpha[abase + i] = e;
        atomicAdd(&hsum[i & 3], e);
    }
    __syncthreads();

    float invden = (deg > 0) ? 1.0f / hsum[h] : 0.f;

    // ---- loop3: weighted aggregation (block-wide, per-thread accumulator) ----
    float acc = 0.f;
    int xlbase = t * NN * HC;
#pragma unroll 4
    for (int k = 0; k < deg; k++) {
        int s = g_srcs[base + k];
        float e = g_alpha[abase + k * 4 + h];
        acc = fmaf(e, g_xl[xlbase + s * HC + tid], acc);
    }
    acc *= invden;

    float o = fmaxf(acc + bias[tid], 0.f);
    out_s[tid] = o;
    __syncthreads();

    // ---- projection: 256 -> 64, 4-way split over j ----
    int part = tid >> 6;
    int c = tid & 63;
    float s = 0.f;
#pragma unroll 8
    for (int j = 0; j < 64; j++) {
        s = fmaf(out_s[part * 64 + j], Wp[(part * 64 + j) * CO + c], s);
    }
    pp[part][c] = s;
    __syncthreads();

    // ---- residual + LayerNorm + relu (threads 0..63) ----
    float v = 0.f;
    if (tid < 64) {
        v = pp[0][tid] + pp[1][tid] + pp[2][tid] + pp[3][tid]
            + bp[tid] + x[(t * NN + n) * CC + tid];
        float sv = v, sq = v * v;
#pragma unroll
        for (int off = 16; off; off >>= 1) {
            sv += __shfl_xor_sync(0xffffffffu, sv, off);
            sq += __shfl_xor_sync(0xffffffffu, sq, off);
        }
        if (lane == 0) { red[wid][0] = sv; red[wid][1] = sq; }
    }
    __syncthreads();
    if (tid < 64) {
        float S = red[0][0] + red[1][0];
        float Q = red[0][1] + red[1][1];
        float mu = S * (1.f / 64.f);
        float var = Q * (1.f / 64.f) - mu * mu;
        float y = (v - mu) * rsqrtf(var + 1e-5f) * gam[tid] + bet[tid];
        out[(t * NN + n) * CC + tid] = fmaxf(y, 0.f);
    }
}

extern "C" void kernel_launch(void* const* d_in, const int* in_sizes, int n_in,
                              void* d_out, int out_size) {
    const float* x    = (const float*)d_in[0];
    const int*   ei   = (const int*)d_in[1];
    const float* Wl   = (const float*)d_in[2];
    const float* bl   = (const float*)d_in[3];
    const float* Wr   = (const float*)d_in[4];
    const float* br   = (const float*)d_in[5];
    const float* att  = (const float*)d_in[6];
    const float* bias = (const float*)d_in[7];
    const float* Wp   = (const float*)d_in[8];
    const float* bp   = (const float*)d_in[9];
    const float* gam  = (const float*)d_in[10];
    const float* bet  = (const float*)d_in[11];
    float* out = (float*)d_out;

    k_zero<<<(NN + 255) / 256, 256>>>();
    k_hist<<<(EE + 255) / 256, 256>>>(ei);
    k_scan<<<1, 1024>>>();
    k_scatter<<<(EE + 255) / 256, 256>>>(ei);
    k_gemm<<<MROWS / 32, 256>>>(x, Wl, bl, Wr, br);
    dim3 g(NN, TT);
    k_node<<<g, 256>>>(x, att, bias, Wp, bp, gam, bet, out);
}